// round 2
// baseline (speedup 1.0000x reference)
#include <cuda_runtime.h>
#include <math.h>

#define SS   4096
#define CC   256
#define BATCH 2
#define NHEAD 4
#define HDIM 64

// Scratch (allocation-free rule: __device__ globals)
__device__ float g_norm[BATCH * CC * SS];        //  8 MB
__device__ float g_qkv [BATCH * 3 * CC * SS];    // 24 MB
__device__ float g_att [BATCH * CC * SS];        //  8 MB

// ---------------------------------------------------------------------------
// GroupNorm: 32 groups of 8 channels. One block per (batch, group).
// ---------------------------------------------------------------------------
__global__ void __launch_bounds__(256) gn_kernel(
    const float* __restrict__ x, const float* __restrict__ w,
    const float* __restrict__ b, float* __restrict__ out)
{
    __shared__ float red[256];
    __shared__ float red2[256];
    int bid = blockIdx.x;
    int bb = bid >> 5, g = bid & 31;
    const float4* src = (const float4*)(x + ((size_t)bb * CC + g * 8) * SS);
    float4* dst = (float4*)(out + ((size_t)bb * CC + g * 8) * SS);
    int tid = threadIdx.x;

    float s = 0.f, ss = 0.f;
    for (int i = tid; i < 8192; i += 256) {
        float4 v = src[i];
        s  += v.x + v.y + v.z + v.w;
        ss += v.x * v.x + v.y * v.y + v.z * v.z + v.w * v.w;
    }
    red[tid] = s; red2[tid] = ss;
    __syncthreads();
    for (int st = 128; st > 0; st >>= 1) {
        if (tid < st) { red[tid] += red[tid + st]; red2[tid] += red2[tid + st]; }
        __syncthreads();
    }
    float mean = red[0] * (1.f / 32768.f);
    float var  = red2[0] * (1.f / 32768.f) - mean * mean;
    float inv  = rsqrtf(var + 1e-5f);

    for (int i = tid; i < 8192; i += 256) {
        int c = g * 8 + (i >> 10);          // 1024 float4 per channel
        float wc = w[c] * inv;
        float bc = b[c] - mean * wc;
        float4 v = src[i];
        v.x = v.x * wc + bc;
        v.y = v.y * wc + bc;
        v.z = v.z * wc + bc;
        v.w = v.w * wc + bc;
        dst[i] = v;
    }
}

// ---------------------------------------------------------------------------
// 1x1 conv == channel GEMM: Y[b][o][s] = sum_c W[o][c] * X[b][c][s]
// Optional epilogue: + bias[o] + resid (residual add for the output proj).
// Tile 64(o) x 64(s), BK=16, 256 threads, 4x4 microtile.
// ---------------------------------------------------------------------------
__global__ void __launch_bounds__(256) conv1x1_kernel(
    const float* __restrict__ W, const float* __restrict__ X,
    float* __restrict__ Y, const float* __restrict__ bias,
    const float* __restrict__ resid, int Cin, int Cout)
{
    __shared__ __align__(16) float Ws[16][68];
    __shared__ __align__(16) float Xs[16][68];
    int tid = threadIdx.x, ty = tid >> 4, tx = tid & 15;
    int s0 = blockIdx.x << 6, o0 = blockIdx.y << 6, bb = blockIdx.z;
    const float* Xb = X + (size_t)bb * Cin * SS;

    float acc[4][4] = {};

    for (int c0 = 0; c0 < Cin; c0 += 16) {
        #pragma unroll
        for (int r = 0; r < 4; r++) {
            int idx = tid + r * 256;
            Ws[idx & 15][idx >> 4] = W[(size_t)(o0 + (idx >> 4)) * Cin + c0 + (idx & 15)];
            Xs[idx >> 6][idx & 63] = Xb[(size_t)(c0 + (idx >> 6)) * SS + s0 + (idx & 63)];
        }
        __syncthreads();
        #pragma unroll
        for (int kk = 0; kk < 16; kk++) {
            float4 a  = *(const float4*)&Ws[kk][ty * 4];
            float4 bx = *(const float4*)&Xs[kk][tx * 4];
            float av[4] = {a.x, a.y, a.z, a.w};
            float bv[4] = {bx.x, bx.y, bx.z, bx.w};
            #pragma unroll
            for (int i = 0; i < 4; i++)
                #pragma unroll
                for (int j = 0; j < 4; j++)
                    acc[i][j] += av[i] * bv[j];
        }
        __syncthreads();
    }

    bool epi = (bias != nullptr);
    #pragma unroll
    for (int i = 0; i < 4; i++) {
        int o = o0 + ty * 4 + i;
        size_t off = ((size_t)bb * Cout + o) * SS + s0 + tx * 4;
        float4 r;
        r.x = acc[i][0]; r.y = acc[i][1]; r.z = acc[i][2]; r.w = acc[i][3];
        if (epi) {
            float bv = bias[o];
            float4 xr = *(const float4*)&resid[off];
            r.x += bv + xr.x; r.y += bv + xr.y; r.z += bv + xr.z; r.w += bv + xr.w;
        }
        *(float4*)&Y[off] = r;
    }
}

// ---------------------------------------------------------------------------
// Flash attention: block = (q_tile 64, head, batch). Online softmax.
// qkv layout per (b, head n): q at channels n*192+[0,64), k +64, v +128.
// Scale 1/sqrt(C)=1/16 folded into Q at load.
// ---------------------------------------------------------------------------
#define FL_SMEM (4 * 64 * 68 * 4)

__global__ void __launch_bounds__(256) flash_kernel(
    const float* __restrict__ qkv, float* __restrict__ att)
{
    extern __shared__ __align__(16) float sm[];
    float* Qs = sm;                 // [64 d][68] (scaled Q, Qs[d][qi])
    float* Ks = Qs + 64 * 68;       // [64 d][68] (Ks[d][kj])
    float* Vt = Ks + 64 * 68;       // [64 t][68] (Vt[kj][d], transposed)
    float* Ps = Vt + 64 * 68;       // [64 q][68] (P tile / output staging)

    const float scale = 0.0625f;    // 1/sqrt(256)
    int qt = blockIdx.x, n = blockIdx.y, bb = blockIdx.z;
    int q0 = qt * 64;
    int tid = threadIdx.x, ty = tid >> 4, tx = tid & 15;

    const float* qbase = qkv + ((size_t)bb * 768 + n * 192) * SS;
    const float* kbase = qbase + (size_t)64  * SS;
    const float* vbase = qbase + (size_t)128 * SS;

    // Load Q tile (64 d x 64 q), scaled
    for (int r = 0; r < 16; r++) {
        int idx = tid + r * 256;
        int d = idx >> 6, qq = idx & 63;
        Qs[d * 68 + qq] = qbase[(size_t)d * SS + q0 + qq] * scale;
    }

    float m[4], l[4], O[4][4];
    #pragma unroll
    for (int i = 0; i < 4; i++) {
        m[i] = -INFINITY; l[i] = 0.f;
        #pragma unroll
        for (int j = 0; j < 4; j++) O[i][j] = 0.f;
    }

    for (int t0 = 0; t0 < SS; t0 += 64) {
        // Load K tile (natural) + V tile (transposed)
        for (int r = 0; r < 16; r++) {
            int idx = tid + r * 256;
            int d = idx >> 6, c = idx & 63;
            float kv = kbase[(size_t)d * SS + t0 + c];
            float vv = vbase[(size_t)d * SS + t0 + c];
            Ks[d * 68 + c] = kv;
            Vt[c * 68 + d] = vv;
        }
        __syncthreads();

        // S = (Q*scale)^T K   — 4x4 microtile per thread
        float p[4][4] = {};
        #pragma unroll 8
        for (int d = 0; d < 64; d++) {
            float4 a  = *(const float4*)&Qs[d * 68 + ty * 4];
            float4 bk = *(const float4*)&Ks[d * 68 + tx * 4];
            float av[4] = {a.x, a.y, a.z, a.w};
            float bv[4] = {bk.x, bk.y, bk.z, bk.w};
            #pragma unroll
            for (int i = 0; i < 4; i++)
                #pragma unroll
                for (int j = 0; j < 4; j++)
                    p[i][j] += av[i] * bv[j];
        }

        // Online softmax row update (rows qi = ty*4+i, reduce over 16 tx lanes)
        #pragma unroll
        for (int i = 0; i < 4; i++) {
            float rmax = fmaxf(fmaxf(p[i][0], p[i][1]), fmaxf(p[i][2], p[i][3]));
            #pragma unroll
            for (int w = 1; w < 16; w <<= 1)
                rmax = fmaxf(rmax, __shfl_xor_sync(0xffffffffu, rmax, w));
            float mn   = fmaxf(m[i], rmax);
            float corr = __expf(m[i] - mn);
            float rs = 0.f;
            #pragma unroll
            for (int j = 0; j < 4; j++) {
                float e = __expf(p[i][j] - mn);
                p[i][j] = e;
                rs += e;
            }
            #pragma unroll
            for (int w = 1; w < 16; w <<= 1)
                rs += __shfl_xor_sync(0xffffffffu, rs, w);
            l[i] = l[i] * corr + rs;
            m[i] = mn;
            #pragma unroll
            for (int j = 0; j < 4; j++) O[i][j] *= corr;
        }

        // Stage P to smem
        #pragma unroll
        for (int i = 0; i < 4; i++) {
            float4 v; v.x = p[i][0]; v.y = p[i][1]; v.z = p[i][2]; v.w = p[i][3];
            *(float4*)&Ps[(ty * 4 + i) * 68 + tx * 4] = v;
        }
        __syncthreads();

        // O[qi][d] += sum_kj P[qi][kj] * V[d][kj]   (cols d = tx*4..)
        #pragma unroll 8
        for (int kj = 0; kj < 64; kj++) {
            float4 bv4 = *(const float4*)&Vt[kj * 68 + tx * 4];
            float bv[4] = {bv4.x, bv4.y, bv4.z, bv4.w};
            float av[4];
            #pragma unroll
            for (int i = 0; i < 4; i++) av[i] = Ps[(ty * 4 + i) * 68 + kj];
            #pragma unroll
            for (int i = 0; i < 4; i++)
                #pragma unroll
                for (int j = 0; j < 4; j++)
                    O[i][j] += av[i] * bv[j];
        }
        __syncthreads();   // before next tile overwrites Ks/Vt/Ps
    }

    // Normalize and stage transposed for coalesced writes: Ps[d][qi]
    #pragma unroll
    for (int i = 0; i < 4; i++) {
        float invl = 1.f / l[i];
        #pragma unroll
        for (int j = 0; j < 4; j++)
            Ps[(tx * 4 + j) * 68 + ty * 4 + i] = O[i][j] * invl;
    }
    __syncthreads();

    float* obase = att + ((size_t)bb * CC + n * HDIM) * SS + q0;
    for (int r = 0; r < 16; r++) {
        int idx = tid + r * 256;
        int d = idx >> 6, qq = idx & 63;
        obase[(size_t)d * SS + qq] = Ps[d * 68 + qq];
    }
}

// ---------------------------------------------------------------------------
extern "C" void kernel_launch(void* const* d_in, const int* in_sizes, int n_in,
                              void* d_out, int out_size)
{
    const float* x     = (const float*)d_in[0];
    const float* gn_w  = (const float*)d_in[1];
    const float* gn_b  = (const float*)d_in[2];
    const float* qkv_w = (const float*)d_in[3];
    const float* o_w   = (const float*)d_in[4];
    const float* o_b   = (const float*)d_in[5];
    float* out = (float*)d_out;

    void *pn, *pq, *pa;
    cudaGetSymbolAddress(&pn, g_norm);
    cudaGetSymbolAddress(&pq, g_qkv);
    cudaGetSymbolAddress(&pa, g_att);
    float* norm = (float*)pn;
    float* qkv  = (float*)pq;
    float* att  = (float*)pa;

    cudaFuncSetAttribute(flash_kernel,
                         cudaFuncAttributeMaxDynamicSharedMemorySize, FL_SMEM);

    // 1. GroupNorm
    gn_kernel<<<BATCH * 32, 256>>>(x, gn_w, gn_b, norm);

    // 2. QKV projection: [768,256] x [B,256,S]
    conv1x1_kernel<<<dim3(SS / 64, 768 / 64, BATCH), 256>>>(
        qkv_w, norm, qkv, nullptr, nullptr, CC, 3 * CC);

    // 3. Flash attention
    flash_kernel<<<dim3(SS / 64, NHEAD, BATCH), 256, FL_SMEM>>>(qkv, att);

    // 4. Output projection + bias + residual
    conv1x1_kernel<<<dim3(SS / 64, CC / 64, BATCH), 256>>>(
        o_w, att, out, o_b, x, CC, CC);
}

// round 3
// speedup vs baseline: 4.0020x; 4.0020x over previous
#include <cuda_runtime.h>
#include <cuda_bf16.h>
#include <math.h>

#define SS   4096
#define CC   256
#define BATCH 2
#define NHEAD 4
#define HDIM 64

// Scratch (allocation-free rule: __device__ globals)
__device__ float g_norm[BATCH * CC * SS];        //  8 MB
__device__ float g_qkv [BATCH * 3 * CC * SS];    // 24 MB
__device__ float g_att [BATCH * CC * SS];        //  8 MB

// ---------------------------------------------------------------------------
// GroupNorm: 32 groups of 8 channels. One block per (batch, group).
// ---------------------------------------------------------------------------
__global__ void __launch_bounds__(256) gn_kernel(
    const float* __restrict__ x, const float* __restrict__ w,
    const float* __restrict__ b, float* __restrict__ out)
{
    __shared__ float red[256];
    __shared__ float red2[256];
    int bid = blockIdx.x;
    int bb = bid >> 5, g = bid & 31;
    const float4* src = (const float4*)(x + ((size_t)bb * CC + g * 8) * SS);
    float4* dst = (float4*)(out + ((size_t)bb * CC + g * 8) * SS);
    int tid = threadIdx.x;

    float s = 0.f, ss = 0.f;
    for (int i = tid; i < 8192; i += 256) {
        float4 v = src[i];
        s  += v.x + v.y + v.z + v.w;
        ss += v.x * v.x + v.y * v.y + v.z * v.z + v.w * v.w;
    }
    red[tid] = s; red2[tid] = ss;
    __syncthreads();
    for (int st = 128; st > 0; st >>= 1) {
        if (tid < st) { red[tid] += red[tid + st]; red2[tid] += red2[tid + st]; }
        __syncthreads();
    }
    float mean = red[0] * (1.f / 32768.f);
    float var  = red2[0] * (1.f / 32768.f) - mean * mean;
    float inv  = rsqrtf(var + 1e-5f);

    for (int i = tid; i < 8192; i += 256) {
        int c = g * 8 + (i >> 10);
        float wc = w[c] * inv;
        float bc = b[c] - mean * wc;
        float4 v = src[i];
        v.x = v.x * wc + bc;
        v.y = v.y * wc + bc;
        v.z = v.z * wc + bc;
        v.w = v.w * wc + bc;
        dst[i] = v;
    }
}

// ---------------------------------------------------------------------------
// 1x1 conv GEMM (fp32) — unchanged from R1.
// ---------------------------------------------------------------------------
__global__ void __launch_bounds__(256) conv1x1_kernel(
    const float* __restrict__ W, const float* __restrict__ X,
    float* __restrict__ Y, const float* __restrict__ bias,
    const float* __restrict__ resid, int Cin, int Cout)
{
    __shared__ __align__(16) float Ws[16][68];
    __shared__ __align__(16) float Xs[16][68];
    int tid = threadIdx.x, ty = tid >> 4, tx = tid & 15;
    int s0 = blockIdx.x << 6, o0 = blockIdx.y << 6, bb = blockIdx.z;
    const float* Xb = X + (size_t)bb * Cin * SS;

    float acc[4][4] = {};

    for (int c0 = 0; c0 < Cin; c0 += 16) {
        #pragma unroll
        for (int r = 0; r < 4; r++) {
            int idx = tid + r * 256;
            Ws[idx & 15][idx >> 4] = W[(size_t)(o0 + (idx >> 4)) * Cin + c0 + (idx & 15)];
            Xs[idx >> 6][idx & 63] = Xb[(size_t)(c0 + (idx >> 6)) * SS + s0 + (idx & 63)];
        }
        __syncthreads();
        #pragma unroll
        for (int kk = 0; kk < 16; kk++) {
            float4 a  = *(const float4*)&Ws[kk][ty * 4];
            float4 bx = *(const float4*)&Xs[kk][tx * 4];
            float av[4] = {a.x, a.y, a.z, a.w};
            float bv[4] = {bx.x, bx.y, bx.z, bx.w};
            #pragma unroll
            for (int i = 0; i < 4; i++)
                #pragma unroll
                for (int j = 0; j < 4; j++)
                    acc[i][j] += av[i] * bv[j];
        }
        __syncthreads();
    }

    bool epi = (bias != nullptr);
    #pragma unroll
    for (int i = 0; i < 4; i++) {
        int o = o0 + ty * 4 + i;
        size_t off = ((size_t)bb * Cout + o) * SS + s0 + tx * 4;
        float4 r;
        r.x = acc[i][0]; r.y = acc[i][1]; r.z = acc[i][2]; r.w = acc[i][3];
        if (epi) {
            float bv = bias[o];
            float4 xr = *(const float4*)&resid[off];
            r.x += bv + xr.x; r.y += bv + xr.y; r.z += bv + xr.z; r.w += bv + xr.w;
        }
        *(float4*)&Y[off] = r;
    }
}

// ---------------------------------------------------------------------------
// Tensor-core flash attention (bf16 HMMA, fp32 accum, online softmax).
// Block = (q_tile 64, head, batch), 4 warps; warp w owns q rows [16w,16w+16).
// qkv per (b, head n): q at channels n*192+[0,64), k +64, v +128.
// Q pre-scaled by (1/sqrt(C)) * log2(e) so softmax uses exp2f.
// ---------------------------------------------------------------------------
__device__ __forceinline__ void mma16816(float c[4], const unsigned a[4],
                                         const unsigned b0, const unsigned b1)
{
    asm volatile(
        "mma.sync.aligned.m16n8k16.row.col.f32.bf16.bf16.f32 "
        "{%0,%1,%2,%3}, {%4,%5,%6,%7}, {%8,%9}, {%0,%1,%2,%3};"
        : "+f"(c[0]), "+f"(c[1]), "+f"(c[2]), "+f"(c[3])
        : "r"(a[0]), "r"(a[1]), "r"(a[2]), "r"(a[3]), "r"(b0), "r"(b1));
}

__device__ __forceinline__ unsigned packbf(float x, float y)
{
    __nv_bfloat162 h = __floats2bfloat162_rn(x, y);
    return *(unsigned*)&h;
}

#define LD 72   // bf16 row stride in smem tiles

__global__ void __launch_bounds__(128) flash_kernel(
    const float* __restrict__ qkv, float* __restrict__ att)
{
    __shared__ __align__(16) __nv_bfloat16 Qs[64 * LD];
    __shared__ __align__(16) __nv_bfloat16 Ks[64 * LD];
    __shared__ __align__(16) __nv_bfloat16 Vs[64 * LD];

    const float scale = 0.0625f * 1.44269504088896340736f; // 1/sqrt(256) * log2(e)
    int qt = blockIdx.x, n = blockIdx.y, bb = blockIdx.z;
    int q0 = qt * 64;
    int tid = threadIdx.x;
    int w = tid >> 5, lane = tid & 31;
    int g = lane >> 2;               // row group 0..7
    int m2 = (lane & 3) * 2;         // col pair 0,2,4,6

    const float* qbase = qkv + ((size_t)bb * 768 + n * 192) * SS;
    const float* kbase = qbase + (size_t)64  * SS;
    const float* vbase = qbase + (size_t)128 * SS;

    // ---- Load Q (transpose [d][s] -> [q][d], scaled, bf16) ----
    for (int r = 0; r < 16; r++) {
        int idx = tid + r * 128;
        int c = idx & 63, d0 = (idx >> 6) * 2;
        float f0 = qbase[(size_t)d0 * SS + q0 + c] * scale;
        float f1 = qbase[(size_t)(d0 + 1) * SS + q0 + c] * scale;
        *(__nv_bfloat162*)&Qs[c * LD + d0] = __floats2bfloat162_rn(f0, f1);
    }
    __syncthreads();

    // ---- Q A-fragments (persist in registers) ----
    unsigned qa[4][4];
    #pragma unroll
    for (int kc = 0; kc < 4; kc++) {
        int qr = w * 16 + g;
        int d0 = kc * 16 + m2;
        qa[kc][0] = *(unsigned*)&Qs[qr * LD + d0];
        qa[kc][1] = *(unsigned*)&Qs[(qr + 8) * LD + d0];
        qa[kc][2] = *(unsigned*)&Qs[qr * LD + d0 + 8];
        qa[kc][3] = *(unsigned*)&Qs[(qr + 8) * LD + d0 + 8];
    }

    float O[8][4] = {};
    float m0 = -INFINITY, m1 = -INFINITY, l0 = 0.f, l1 = 0.f;

    for (int t0 = 0; t0 < SS; t0 += 64) {
        __syncthreads();   // prior iteration's mma reads of Ks/Vs complete

        // K: transpose [d][t] -> Ks[k][d] bf16
        for (int r = 0; r < 16; r++) {
            int idx = tid + r * 128;
            int c = idx & 63, d0 = (idx >> 6) * 2;
            float f0 = kbase[(size_t)d0 * SS + t0 + c];
            float f1 = kbase[(size_t)(d0 + 1) * SS + t0 + c];
            *(__nv_bfloat162*)&Ks[c * LD + d0] = __floats2bfloat162_rn(f0, f1);
        }
        // V: natural [d][t] -> Vs[d][k] bf16 (float4 loads)
        for (int r = 0; r < 8; r++) {
            int idx = tid + r * 128;
            int d = idx >> 4, c4 = (idx & 15) * 4;
            float4 v = *(const float4*)&vbase[(size_t)d * SS + t0 + c4];
            *(__nv_bfloat162*)&Vs[d * LD + c4]     = __floats2bfloat162_rn(v.x, v.y);
            *(__nv_bfloat162*)&Vs[d * LD + c4 + 2] = __floats2bfloat162_rn(v.z, v.w);
        }
        __syncthreads();

        // ---- S = Q K^T : 8 n-tiles (8 keys each) x 4 k-chunks (16 d each) ----
        float S[8][4] = {};
        #pragma unroll
        for (int nt = 0; nt < 8; nt++) {
            int kb = (nt * 8 + g) * LD;
            #pragma unroll
            for (int kc = 0; kc < 4; kc++) {
                unsigned b0 = *(unsigned*)&Ks[kb + kc * 16 + m2];
                unsigned b1 = *(unsigned*)&Ks[kb + kc * 16 + m2 + 8];
                mma16816(S[nt], qa[kc], b0, b1);
            }
        }

        // ---- online softmax (rows r0 = w*16+g, r1 = r0+8) ----
        float vmax0 = -INFINITY, vmax1 = -INFINITY;
        #pragma unroll
        for (int nt = 0; nt < 8; nt++) {
            vmax0 = fmaxf(vmax0, fmaxf(S[nt][0], S[nt][1]));
            vmax1 = fmaxf(vmax1, fmaxf(S[nt][2], S[nt][3]));
        }
        vmax0 = fmaxf(vmax0, __shfl_xor_sync(0xffffffffu, vmax0, 1));
        vmax0 = fmaxf(vmax0, __shfl_xor_sync(0xffffffffu, vmax0, 2));
        vmax1 = fmaxf(vmax1, __shfl_xor_sync(0xffffffffu, vmax1, 1));
        vmax1 = fmaxf(vmax1, __shfl_xor_sync(0xffffffffu, vmax1, 2));

        float mn0 = fmaxf(m0, vmax0), mn1 = fmaxf(m1, vmax1);
        float corr0 = exp2f(m0 - mn0), corr1 = exp2f(m1 - mn1);
        m0 = mn0; m1 = mn1;

        float rs0 = 0.f, rs1 = 0.f;
        #pragma unroll
        for (int nt = 0; nt < 8; nt++) {
            S[nt][0] = exp2f(S[nt][0] - mn0);
            S[nt][1] = exp2f(S[nt][1] - mn0);
            S[nt][2] = exp2f(S[nt][2] - mn1);
            S[nt][3] = exp2f(S[nt][3] - mn1);
            rs0 += S[nt][0] + S[nt][1];
            rs1 += S[nt][2] + S[nt][3];
        }
        rs0 += __shfl_xor_sync(0xffffffffu, rs0, 1);
        rs0 += __shfl_xor_sync(0xffffffffu, rs0, 2);
        rs1 += __shfl_xor_sync(0xffffffffu, rs1, 1);
        rs1 += __shfl_xor_sync(0xffffffffu, rs1, 2);
        l0 = l0 * corr0 + rs0;
        l1 = l1 * corr1 + rs1;

        #pragma unroll
        for (int nt = 0; nt < 8; nt++) {
            O[nt][0] *= corr0; O[nt][1] *= corr0;
            O[nt][2] *= corr1; O[nt][3] *= corr1;
        }

        // ---- P (C-fragment pairs) -> bf16 A-fragments, no smem round trip ----
        unsigned pa[4][4];
        #pragma unroll
        for (int kc = 0; kc < 4; kc++) {
            pa[kc][0] = packbf(S[2 * kc][0],     S[2 * kc][1]);
            pa[kc][1] = packbf(S[2 * kc][2],     S[2 * kc][3]);
            pa[kc][2] = packbf(S[2 * kc + 1][0], S[2 * kc + 1][1]);
            pa[kc][3] = packbf(S[2 * kc + 1][2], S[2 * kc + 1][3]);
        }

        // ---- O += P V : 8 d-tiles x 4 kj-chunks ----
        #pragma unroll
        for (int nt = 0; nt < 8; nt++) {
            int vb = (nt * 8 + g) * LD;
            #pragma unroll
            for (int kc = 0; kc < 4; kc++) {
                unsigned b0 = *(unsigned*)&Vs[vb + kc * 16 + m2];
                unsigned b1 = *(unsigned*)&Vs[vb + kc * 16 + m2 + 8];
                mma16816(O[nt], pa[kc], b0, b1);
            }
        }
    }

    // ---- epilogue: normalize, stage [d][q] fp32 (overlay Qs+Ks), write ----
    __syncthreads();
    float* Os = (float*)Qs;   // 64*68 floats = 17408 B <= Qs+Ks (18432 B)
    float invl0 = 1.f / l0, invl1 = 1.f / l1;
    int qr = w * 16 + g;
    #pragma unroll
    for (int nt = 0; nt < 8; nt++) {
        int d0 = nt * 8 + m2;
        Os[d0 * 68 + qr]           = O[nt][0] * invl0;
        Os[(d0 + 1) * 68 + qr]     = O[nt][1] * invl0;
        Os[d0 * 68 + qr + 8]       = O[nt][2] * invl1;
        Os[(d0 + 1) * 68 + qr + 8] = O[nt][3] * invl1;
    }
    __syncthreads();

    float* obase = att + ((size_t)bb * CC + n * HDIM) * SS + q0;
    for (int r = 0; r < 32; r++) {
        int idx = tid + r * 128;
        int d = idx >> 6, qq = idx & 63;
        obase[(size_t)d * SS + qq] = Os[d * 68 + qq];
    }
}

// ---------------------------------------------------------------------------
extern "C" void kernel_launch(void* const* d_in, const int* in_sizes, int n_in,
                              void* d_out, int out_size)
{
    const float* x     = (const float*)d_in[0];
    const float* gn_w  = (const float*)d_in[1];
    const float* gn_b  = (const float*)d_in[2];
    const float* qkv_w = (const float*)d_in[3];
    const float* o_w   = (const float*)d_in[4];
    const float* o_b   = (const float*)d_in[5];
    float* out = (float*)d_out;

    void *pn, *pq, *pa;
    cudaGetSymbolAddress(&pn, g_norm);
    cudaGetSymbolAddress(&pq, g_qkv);
    cudaGetSymbolAddress(&pa, g_att);
    float* norm = (float*)pn;
    float* qkv  = (float*)pq;
    float* att  = (float*)pa;

    // 1. GroupNorm
    gn_kernel<<<BATCH * 32, 256>>>(x, gn_w, gn_b, norm);

    // 2. QKV projection: [768,256] x [B,256,S]
    conv1x1_kernel<<<dim3(SS / 64, 768 / 64, BATCH), 256>>>(
        qkv_w, norm, qkv, nullptr, nullptr, CC, 3 * CC);

    // 3. Flash attention (bf16 tensor cores)
    flash_kernel<<<dim3(SS / 64, NHEAD, BATCH), 128>>>(qkv, att);

    // 4. Output projection + bias + residual
    conv1x1_kernel<<<dim3(SS / 64, CC / 64, BATCH), 256>>>(
        o_w, att, out, o_b, x, CC, CC);
}

// round 4
// speedup vs baseline: 10.8612x; 2.7140x over previous
#include <cuda_runtime.h>
#include <cuda_bf16.h>
#include <math.h>

#define SS   4096
#define CC   256
#define BATCH 2

typedef __nv_bfloat16  bf16;
typedef __nv_bfloat162 bf162;

// Scratch (__device__ globals; no allocation allowed)
__device__ bf16 g_norm[BATCH * CC * SS];          // GN output, [b][c][s] bf16
__device__ bf16 g_qkv [BATCH * 3 * CC * SS];      // QKV GEMM output, [b][o][s] bf16
__device__ bf16 g_att [BATCH * SS * CC];          // attention out, [b][s][c] bf16
__device__ bf16 g_wb  [(3 * CC + CC) * CC];       // bf16 weights: qkv_w then o_w

// ---------------------------------------------------------------------------
// PTX helpers
// ---------------------------------------------------------------------------
__device__ __forceinline__ unsigned sptr(const void* p) {
    return (unsigned)__cvta_generic_to_shared(p);
}
__device__ __forceinline__ void cpasync16(void* dst, const void* src) {
    asm volatile("cp.async.cg.shared.global [%0], [%1], 16;\n"
                 :: "r"(sptr(dst)), "l"(src));
}
__device__ __forceinline__ void cpcommit() {
    asm volatile("cp.async.commit_group;\n");
}
template<int N> __device__ __forceinline__ void cpwait() {
    asm volatile("cp.async.wait_group %0;\n" :: "n"(N));
}
__device__ __forceinline__ void ldm_x4(unsigned& r0, unsigned& r1, unsigned& r2,
                                       unsigned& r3, const void* p) {
    asm volatile("ldmatrix.sync.aligned.m8n8.x4.shared.b16 {%0,%1,%2,%3}, [%4];\n"
                 : "=r"(r0), "=r"(r1), "=r"(r2), "=r"(r3) : "r"(sptr(p)));
}
__device__ __forceinline__ void ldm_x4t(unsigned& r0, unsigned& r1, unsigned& r2,
                                        unsigned& r3, const void* p) {
    asm volatile("ldmatrix.sync.aligned.m8n8.x4.trans.shared.b16 {%0,%1,%2,%3}, [%4];\n"
                 : "=r"(r0), "=r"(r1), "=r"(r2), "=r"(r3) : "r"(sptr(p)));
}
__device__ __forceinline__ void ldm_x2(unsigned& r0, unsigned& r1, const void* p) {
    asm volatile("ldmatrix.sync.aligned.m8n8.x2.shared.b16 {%0,%1}, [%2];\n"
                 : "=r"(r0), "=r"(r1) : "r"(sptr(p)));
}
__device__ __forceinline__ void ldm_x2t(unsigned& r0, unsigned& r1, const void* p) {
    asm volatile("ldmatrix.sync.aligned.m8n8.x2.trans.shared.b16 {%0,%1}, [%2];\n"
                 : "=r"(r0), "=r"(r1) : "r"(sptr(p)));
}
__device__ __forceinline__ void mma16816(float c[4], const unsigned a[4],
                                         unsigned b0, unsigned b1) {
    asm volatile(
        "mma.sync.aligned.m16n8k16.row.col.f32.bf16.bf16.f32 "
        "{%0,%1,%2,%3}, {%4,%5,%6,%7}, {%8,%9}, {%0,%1,%2,%3};"
        : "+f"(c[0]), "+f"(c[1]), "+f"(c[2]), "+f"(c[3])
        : "r"(a[0]), "r"(a[1]), "r"(a[2]), "r"(a[3]), "r"(b0), "r"(b1));
}
__device__ __forceinline__ unsigned packbf(float x, float y) {
    bf162 h = __floats2bfloat162_rn(x, y);
    return *(unsigned*)&h;
}

// ---------------------------------------------------------------------------
// GroupNorm -> bf16 [c][s]. One block per (batch, group of 8 channels).
// ---------------------------------------------------------------------------
__global__ void __launch_bounds__(256) gn_kernel(
    const float* __restrict__ x, const float* __restrict__ w,
    const float* __restrict__ b, bf16* __restrict__ out)
{
    __shared__ float red[256];
    __shared__ float red2[256];
    int bid = blockIdx.x;
    int bb = bid >> 5, g = bid & 31;
    const float4* src = (const float4*)(x + ((size_t)bb * CC + g * 8) * SS);
    bf162* dst = (bf162*)(out + ((size_t)bb * CC + g * 8) * SS);
    int tid = threadIdx.x;

    float s = 0.f, ss = 0.f;
    for (int i = tid; i < 8192; i += 256) {
        float4 v = src[i];
        s  += v.x + v.y + v.z + v.w;
        ss += v.x * v.x + v.y * v.y + v.z * v.z + v.w * v.w;
    }
    red[tid] = s; red2[tid] = ss;
    __syncthreads();
    for (int st = 128; st > 0; st >>= 1) {
        if (tid < st) { red[tid] += red[tid + st]; red2[tid] += red2[tid + st]; }
        __syncthreads();
    }
    float mean = red[0] * (1.f / 32768.f);
    float var  = red2[0] * (1.f / 32768.f) - mean * mean;
    float inv  = rsqrtf(var + 1e-5f);

    for (int i = tid; i < 8192; i += 256) {
        int c = g * 8 + (i >> 10);
        float wc = w[c] * inv;
        float bc = b[c] - mean * wc;
        float4 v = src[i];
        dst[2 * i]     = __floats2bfloat162_rn(v.x * wc + bc, v.y * wc + bc);
        dst[2 * i + 1] = __floats2bfloat162_rn(v.z * wc + bc, v.w * wc + bc);
    }
}

// ---------------------------------------------------------------------------
// Weight convert fp32 -> bf16 (qkv_w 196608 + o_w 65536)
// ---------------------------------------------------------------------------
__global__ void __launch_bounds__(256) wcvt_kernel(
    const float* __restrict__ wq, const float* __restrict__ wo, bf16* __restrict__ out)
{
    int i = blockIdx.x * 256 + threadIdx.x;
    if (i < 196608) out[i] = __float2bfloat16(wq[i]);
    else if (i < 262144) out[i] = __float2bfloat16(wo[i - 196608]);
}

// ---------------------------------------------------------------------------
// bf16 tensor-core GEMM: Y[o][s] = sum_c W[o][c] * X[c][s]
//  TRB=1: X stored [c][s] (ldmatrix.trans B)     -> QKV path, bf16 out [o][s]
//  TRB=0: X stored [s][c] (ldmatrix B)           -> o-proj, fp32 out + bias + resid
// Block tile: M=64(o) x N=128(s), K=256 in 32-chunks, double-buffered cp.async.
// ---------------------------------------------------------------------------
template<int TRB, int EPI>
__global__ void __launch_bounds__(256) gemm_kernel(
    const bf16* __restrict__ Wg, const bf16* __restrict__ Xg,
    bf16* __restrict__ Yb, float* __restrict__ Yf,
    const float* __restrict__ bias, const float* __restrict__ resid, int Cout)
{
    __shared__ __align__(16) bf16 Ws[2][64 * 40];
    __shared__ __align__(16) bf16 Xs[2][TRB ? 32 * 136 : 128 * 40];

    int tid = threadIdx.x;
    int s0 = blockIdx.x * 128, o0 = blockIdx.y * 64, bb = blockIdx.z;
    const bf16* Xb = Xg + (size_t)bb * CC * SS;

    int w = tid >> 5, lane = tid & 31;
    int wm = w >> 2, wn = w & 3;
    int g = lane >> 2, m2 = (lane & 3) * 2;
    int lr = (lane & 7) | (lane & 8);            // x2 ldmatrix row 0..15
    int q8 = (lane >> 3) & 1, k8 = (lane >> 4) & 1;

    // loaders
    auto issue = [&](int c0, int st) {
        { int row = tid >> 2, ch = tid & 3;
          cpasync16(&Ws[st][row * 40 + ch * 8],
                    Wg + (size_t)(o0 + row) * CC + c0 + ch * 8); }
        if (TRB) {
            #pragma unroll
            for (int p = 0; p < 2; p++) {
                int idx = tid + p * 256, row = idx >> 4, ch = idx & 15;
                cpasync16(&Xs[st][row * 136 + ch * 8],
                          Xb + (size_t)(c0 + row) * SS + s0 + ch * 8);
            }
        } else {
            #pragma unroll
            for (int p = 0; p < 2; p++) {
                int idx = tid + p * 256, row = idx >> 2, ch = idx & 3;
                cpasync16(&Xs[st][row * 40 + ch * 8],
                          Xb + (size_t)(s0 + row) * CC + c0 + ch * 8);
            }
        }
    };

    issue(0, 0);  cpcommit();
    issue(32, 1); cpcommit();

    float C[2][4][4] = {};

    for (int kc8 = 0; kc8 < 8; kc8++) {
        int st = kc8 & 1;
        if (kc8 < 7) cpwait<1>(); else cpwait<0>();
        __syncthreads();

        #pragma unroll
        for (int kc = 0; kc < 2; kc++) {
            unsigned a[2][4];
            #pragma unroll
            for (int mt = 0; mt < 2; mt++)
                ldm_x4(a[mt][0], a[mt][1], a[mt][2], a[mt][3],
                       &Ws[st][(wm * 32 + mt * 16 + q8 * 8 + (lane & 7)) * 40
                               + kc * 16 + k8 * 8]);
            #pragma unroll
            for (int j = 0; j < 4; j++) {
                unsigned b0, b1;
                if (TRB)
                    ldm_x2t(b0, b1, &Xs[st][(kc * 16 + lr) * 136 + wn * 32 + j * 8]);
                else
                    ldm_x2(b0, b1, &Xs[st][(wn * 32 + j * 8 + (lane & 7)) * 40
                                           + kc * 16 + ((lane & 8) ? 8 : 0)]);
                #pragma unroll
                for (int mt = 0; mt < 2; mt++)
                    mma16816(C[mt][j], a[mt], b0, b1);
            }
        }
        __syncthreads();
        if (kc8 + 2 < 8) { issue((kc8 + 2) * 32, st); cpcommit(); }
    }

    // epilogue
    #pragma unroll
    for (int mt = 0; mt < 2; mt++) {
        #pragma unroll
        for (int j = 0; j < 4; j++) {
            int o = o0 + wm * 32 + mt * 16 + g;
            int s = s0 + wn * 32 + j * 8 + m2;
            if (EPI == 0) {
                bf16* Y = Yb + (size_t)bb * Cout * SS;
                *(bf162*)&Y[(size_t)o * SS + s] =
                    __floats2bfloat162_rn(C[mt][j][0], C[mt][j][1]);
                *(bf162*)&Y[(size_t)(o + 8) * SS + s] =
                    __floats2bfloat162_rn(C[mt][j][2], C[mt][j][3]);
            } else {
                float* Y = Yf + (size_t)bb * CC * SS;
                const float* R = resid + (size_t)bb * CC * SS;
                float bv0 = bias[o], bv1 = bias[o + 8];
                float2 r0 = *(const float2*)&R[(size_t)o * SS + s];
                float2 r1 = *(const float2*)&R[(size_t)(o + 8) * SS + s];
                float2 y0 = { C[mt][j][0] + bv0 + r0.x, C[mt][j][1] + bv0 + r0.y };
                float2 y1 = { C[mt][j][2] + bv1 + r1.x, C[mt][j][3] + bv1 + r1.y };
                *(float2*)&Y[(size_t)o * SS + s] = y0;
                *(float2*)&Y[(size_t)(o + 8) * SS + s] = y1;
            }
        }
    }
}

// ---------------------------------------------------------------------------
// Flash attention, bf16 HMMA, q-tile 128, 8 warps, cp.async double buffer.
// qkv bf16 [b][o][s]; head n: q ch n*192+[0,64), k +64, v +128.
// Softmax scale (1/16 * log2e) folded into the exp2 FMA.
// Output att bf16 [b][s][c], c = n*64+d.
// ---------------------------------------------------------------------------
#define KLD 72
#define QLD 136
#define FL_SMEM ((64 * QLD + 4 * 64 * KLD) * 2)

__global__ void __launch_bounds__(256) flash_kernel(
    const bf16* __restrict__ qkv, bf16* __restrict__ att)
{
    extern __shared__ __align__(16) bf16 sm[];
    bf16* Qs = sm;                        // [64 d][QLD]
    bf16* Kst[2] = { sm + 64 * QLD,              sm + 64 * QLD + 2 * 64 * KLD };
    bf16* Vst[2] = { sm + 64 * QLD + 64 * KLD,   sm + 64 * QLD + 3 * 64 * KLD };

    const float scale = 0.0625f * 1.44269504088896340736f;
    int q0 = blockIdx.x * 128, n = blockIdx.y, bb = blockIdx.z;
    int tid = threadIdx.x;
    int w = tid >> 5, lane = tid & 31;
    int g = lane >> 2, m2 = (lane & 3) * 2;
    int lr = (lane & 7) | (lane & 8);
    int q8 = (lane >> 3) & 1, k8 = (lane >> 4) & 1;

    const bf16* qbase = qkv + ((size_t)bb * 768 + n * 192) * SS;
    const bf16* kbase = qbase + (size_t)64  * SS;
    const bf16* vbase = qbase + (size_t)128 * SS;

    // Q: [64 d][128 q] natural copy
    #pragma unroll
    for (int p = 0; p < 4; p++) {
        int idx = tid + p * 256, row = idx >> 4, ch = idx & 15;
        cpasync16(&Qs[row * QLD + ch * 8], qbase + (size_t)row * SS + q0 + ch * 8);
    }
    cpcommit();

    auto issueKV = [&](int t0, int st) {
        #pragma unroll
        for (int p = 0; p < 2; p++) {
            int idx = tid + p * 256, row = idx >> 3, ch = idx & 7;
            cpasync16(&Kst[st][row * KLD + ch * 8],
                      kbase + (size_t)row * SS + t0 + ch * 8);
            cpasync16(&Vst[st][row * KLD + ch * 8],
                      vbase + (size_t)row * SS + t0 + ch * 8);
        }
    };
    issueKV(0, 0); cpcommit();

    cpwait<1>();      // Q ready
    __syncthreads();

    // Q A-fragments from [d][q] via ldmatrix.trans (once)
    unsigned qa[4][4];
    #pragma unroll
    for (int kc = 0; kc < 4; kc++)
        ldm_x4t(qa[kc][0], qa[kc][1], qa[kc][2], qa[kc][3],
                &Qs[(kc * 16 + k8 * 8 + (lane & 7)) * QLD + w * 16 + q8 * 8]);

    float O[8][4] = {};
    float m0 = -INFINITY, m1 = -INFINITY, l0 = 0.f, l1 = 0.f;

    for (int t = 0; t < 64; t++) {
        int st = t & 1;
        if (t < 63) { issueKV((t + 1) * 64, st ^ 1); cpcommit(); cpwait<1>(); }
        else        cpwait<0>();
        __syncthreads();

        // S = Q K^T (raw, unscaled)
        float S[8][4] = {};
        #pragma unroll
        for (int nt = 0; nt < 8; nt++) {
            #pragma unroll
            for (int kc = 0; kc < 4; kc++) {
                unsigned b0, b1;
                ldm_x2t(b0, b1, &Kst[st][(kc * 16 + lr) * KLD + nt * 8]);
                mma16816(S[nt], qa[kc], b0, b1);
            }
        }

        // online softmax in scaled (log2) domain
        float vmax0 = -INFINITY, vmax1 = -INFINITY;
        #pragma unroll
        for (int nt = 0; nt < 8; nt++) {
            vmax0 = fmaxf(vmax0, fmaxf(S[nt][0], S[nt][1]));
            vmax1 = fmaxf(vmax1, fmaxf(S[nt][2], S[nt][3]));
        }
        vmax0 = fmaxf(vmax0, __shfl_xor_sync(0xffffffffu, vmax0, 1));
        vmax0 = fmaxf(vmax0, __shfl_xor_sync(0xffffffffu, vmax0, 2));
        vmax1 = fmaxf(vmax1, __shfl_xor_sync(0xffffffffu, vmax1, 1));
        vmax1 = fmaxf(vmax1, __shfl_xor_sync(0xffffffffu, vmax1, 2));

        float mn0 = fmaxf(m0, vmax0 * scale), mn1 = fmaxf(m1, vmax1 * scale);
        float corr0 = exp2f(m0 - mn0), corr1 = exp2f(m1 - mn1);
        m0 = mn0; m1 = mn1;

        float rs0 = 0.f, rs1 = 0.f;
        #pragma unroll
        for (int nt = 0; nt < 8; nt++) {
            S[nt][0] = exp2f(fmaf(S[nt][0], scale, -mn0));
            S[nt][1] = exp2f(fmaf(S[nt][1], scale, -mn0));
            S[nt][2] = exp2f(fmaf(S[nt][2], scale, -mn1));
            S[nt][3] = exp2f(fmaf(S[nt][3], scale, -mn1));
            rs0 += S[nt][0] + S[nt][1];
            rs1 += S[nt][2] + S[nt][3];
        }
        rs0 += __shfl_xor_sync(0xffffffffu, rs0, 1);
        rs0 += __shfl_xor_sync(0xffffffffu, rs0, 2);
        rs1 += __shfl_xor_sync(0xffffffffu, rs1, 1);
        rs1 += __shfl_xor_sync(0xffffffffu, rs1, 2);
        l0 = l0 * corr0 + rs0;
        l1 = l1 * corr1 + rs1;

        #pragma unroll
        for (int nt = 0; nt < 8; nt++) {
            O[nt][0] *= corr0; O[nt][1] *= corr0;
            O[nt][2] *= corr1; O[nt][3] *= corr1;
        }

        // P C-frags -> bf16 A-frags (register permutation)
        unsigned pa[4][4];
        #pragma unroll
        for (int kc = 0; kc < 4; kc++) {
            pa[kc][0] = packbf(S[2 * kc][0],     S[2 * kc][1]);
            pa[kc][1] = packbf(S[2 * kc][2],     S[2 * kc][3]);
            pa[kc][2] = packbf(S[2 * kc + 1][0], S[2 * kc + 1][1]);
            pa[kc][3] = packbf(S[2 * kc + 1][2], S[2 * kc + 1][3]);
        }

        // O += P V  (V natural [d][k]; plain 32-bit LDS B-frags)
        #pragma unroll
        for (int nt = 0; nt < 8; nt++) {
            int vb = (nt * 8 + g) * KLD;
            #pragma unroll
            for (int kc = 0; kc < 4; kc++) {
                unsigned b0 = *(unsigned*)&Vst[st][vb + kc * 16 + m2];
                unsigned b1 = *(unsigned*)&Vst[st][vb + kc * 16 + m2 + 8];
                mma16816(O[nt], pa[kc], b0, b1);
            }
        }
        __syncthreads();
    }

    // epilogue: att[b][s][c] bf16, direct frag stores
    float invl0 = 1.f / l0, invl1 = 1.f / l1;
    bf16* ab = att + ((size_t)bb * SS + q0) * CC + n * 64;
    int qr = w * 16 + g;
    #pragma unroll
    for (int nt = 0; nt < 8; nt++) {
        *(bf162*)&ab[(size_t)qr * CC + nt * 8 + m2] =
            __floats2bfloat162_rn(O[nt][0] * invl0, O[nt][1] * invl0);
        *(bf162*)&ab[(size_t)(qr + 8) * CC + nt * 8 + m2] =
            __floats2bfloat162_rn(O[nt][2] * invl1, O[nt][3] * invl1);
    }
}

// ---------------------------------------------------------------------------
extern "C" void kernel_launch(void* const* d_in, const int* in_sizes, int n_in,
                              void* d_out, int out_size)
{
    const float* x     = (const float*)d_in[0];
    const float* gn_w  = (const float*)d_in[1];
    const float* gn_b  = (const float*)d_in[2];
    const float* qkv_w = (const float*)d_in[3];
    const float* o_w   = (const float*)d_in[4];
    const float* o_b   = (const float*)d_in[5];
    float* out = (float*)d_out;

    void *pn, *pq, *pa, *pw;
    cudaGetSymbolAddress(&pn, g_norm);
    cudaGetSymbolAddress(&pq, g_qkv);
    cudaGetSymbolAddress(&pa, g_att);
    cudaGetSymbolAddress(&pw, g_wb);
    bf16* norm = (bf16*)pn;
    bf16* qkv  = (bf16*)pq;
    bf16* att  = (bf16*)pa;
    bf16* wb   = (bf16*)pw;

    cudaFuncSetAttribute(flash_kernel,
                         cudaFuncAttributeMaxDynamicSharedMemorySize, FL_SMEM);

    // 1. GroupNorm -> bf16 [c][s]
    gn_kernel<<<BATCH * 32, 256>>>(x, gn_w, gn_b, norm);

    // 2. Weights -> bf16
    wcvt_kernel<<<1024, 256>>>(qkv_w, o_w, wb);

    // 3. QKV GEMM (bf16 tensor cores): [768,256] x [256,S] -> bf16 [o][s]
    gemm_kernel<1, 0><<<dim3(32, 12, BATCH), 256>>>(
        wb, norm, qkv, nullptr, nullptr, nullptr, 3 * CC);

    // 4. Flash attention -> att bf16 [s][c]
    flash_kernel<<<dim3(32, 4, BATCH), 256, FL_SMEM>>>(qkv, att);

    // 5. O-proj GEMM + bias + residual (fp32 out)
    gemm_kernel<0, 1><<<dim3(32, 4, BATCH), 256>>>(
        wb + 196608, att, nullptr, out, o_b, x, CC);
}